// round 8
// baseline (speedup 1.0000x reference)
#include <cuda_runtime.h>
#include <cuda_bf16.h>
#include <math.h>

#define NNODE 5000
#define NEDGE 50000
#define FDIM 64

// ---------------- device scratch ----------------
__device__ float g0buf[NNODE * 64];
__device__ float g1buf[NNODE * 192];   // [n][c(3)][f(64)]
__device__ float g2buf[NNODE * 320];   // [n][c(5)][f(64)]
__device__ float abuf[NNODE * 2752];   // [n][ a0(192) | a1(960) | a2(1600) ]
__device__ float d_CG[504];
// interleaved weight buffers (filled by transpose_kernel each call)
__device__ float wm3t[13 * 16 * 64 * 4];   // [(m*16+fo)*64+ft][fi]
__device__ float wd0t[48 * 192 * 4];       // [(mo*192+t)][fi]
__device__ float wd1t[80 * 64 * 4];        // [(mo*64+f)][fi]
__device__ float wd2t[80 * 64 * 4];

#define OFF110 0
#define OFF220 9
#define OFF121 34
#define OFF211 79
#define OFF231 124
#define OFF112 229
#define OFF132 274
#define OFF222 379

// ---------------- packed f32x2 helpers ----------------
__device__ __forceinline__ unsigned long long fma2(unsigned long long a,
                                                   unsigned long long b,
                                                   unsigned long long c) {
    unsigned long long d;
    asm("fma.rn.f32x2 %0, %1, %2, %3;" : "=l"(d) : "l"(a), "l"(b), "l"(c));
    return d;
}
__device__ __forceinline__ unsigned long long pack2(float w) {
    unsigned long long d;
    asm("mov.b64 %0, {%1, %1};" : "=l"(d) : "f"(w));
    return d;
}
__device__ __forceinline__ void unpack2(unsigned long long v, float& lo, float& hi) {
    asm("mov.b64 {%0, %1}, %2;" : "=f"(lo), "=f"(hi) : "l"(v));
}

// ---------------- CG coefficient computation (exact, device-side) ----------------
__device__ __forceinline__ double dfact(int n) {
    const double F[10] = {1., 1., 2., 6., 24., 120., 720., 5040., 40320., 362880.};
    return F[n];
}

__device__ double cgc(int j1, int m1, int j2, int m2, int j3, int m3) {
    if (m1 + m2 != m3) return 0.0;
    int lo = j1 - j2; if (lo < 0) lo = -lo;
    if (j3 < lo || j3 > j1 + j2) return 0.0;
    double pref = sqrt((2.0 * j3 + 1.0) * dfact(j3 + j1 - j2) * dfact(j3 - j1 + j2) *
                       dfact(j1 + j2 - j3) / dfact(j1 + j2 + j3 + 1));
    pref *= sqrt(dfact(j3 + m3) * dfact(j3 - m3) * dfact(j1 - m1) * dfact(j1 + m1) *
                 dfact(j2 - m2) * dfact(j2 + m2));
    double s = 0.0;
    for (int k = 0; k <= j1 + j2 + j3; k++) {
        int d0 = j1 + j2 - j3 - k, d1 = j1 - m1 - k, d2 = j2 + m2 - k;
        int d3 = j3 - j2 + m1 + k, d4 = j3 - j1 - m2 + k;
        if (d0 < 0 || d1 < 0 || d2 < 0 || d3 < 0 || d4 < 0) continue;
        double term = 1.0 / (dfact(k) * dfact(d0) * dfact(d1) * dfact(d2) * dfact(d3) * dfact(d4));
        s += (k & 1) ? -term : term;
    }
    return pref * s;
}

__device__ double2 Umat(int l, int i, int a) {
    const double s = 0.70710678118654752440;
    int mi = i - l;
    if (mi == 0) return (a == l) ? make_double2(1.0, 0.0) : make_double2(0.0, 0.0);
    if (mi > 0) {
        int m = mi; double sgn = (m & 1) ? -1.0 : 1.0;
        if (a == l + m) return make_double2(sgn * s, 0.0);
        if (a == l - m) return make_double2(s, 0.0);
    } else {
        int m = -mi; double sgn = (m & 1) ? -1.0 : 1.0;
        if (a == l - m) return make_double2(0.0, s);
        if (a == l + m) return make_double2(0.0, -sgn * s);
    }
    return make_double2(0.0, 0.0);
}

__device__ float realcg(int l1, int l2, int l3, int i, int j, int k) {
    double re = 0.0;
    int d1 = 2 * l1 + 1, d2 = 2 * l2 + 1, d3 = 2 * l3 + 1;
    for (int a = 0; a < d1; a++) {
        double2 u1 = Umat(l1, i, a);
        if (u1.x == 0.0 && u1.y == 0.0) continue;
        for (int b = 0; b < d2; b++) {
            double2 u2 = Umat(l2, j, b);
            if (u2.x == 0.0 && u2.y == 0.0) continue;
            double pr = u1.x * u2.x - u1.y * u2.y;
            double pi = u1.x * u2.y + u1.y * u2.x;
            for (int c = 0; c < d3; c++) {
                double2 u3 = Umat(l3, k, c);
                u3.y = -u3.y;
                if (u3.x == 0.0 && u3.y == 0.0) continue;
                double cg = cgc(l1, a - l1, l2, b - l2, l3, c - l3);
                if (cg == 0.0) continue;
                re += (pr * u3.x - pi * u3.y) * cg;
            }
        }
    }
    return (float)re;
}

__global__ void cg_init_kernel() {
    int idx = blockIdx.x * blockDim.x + threadIdx.x;
    if (idx >= 504) return;
    int l1, l2, l3, flat;
    if (idx < 9)        { l1 = 1; l2 = 1; l3 = 0; flat = idx; }
    else if (idx < 34)  { l1 = 2; l2 = 2; l3 = 0; flat = idx - 9; }
    else if (idx < 79)  { l1 = 1; l2 = 2; l3 = 1; flat = idx - 34; }
    else if (idx < 124) { l1 = 2; l2 = 1; l3 = 1; flat = idx - 79; }
    else if (idx < 229) { l1 = 2; l2 = 3; l3 = 1; flat = idx - 124; }
    else if (idx < 274) { l1 = 1; l2 = 1; l3 = 2; flat = idx - 229; }
    else if (idx < 379) { l1 = 1; l2 = 3; l3 = 2; flat = idx - 274; }
    else                { l1 = 2; l2 = 2; l3 = 2; flat = idx - 379; }
    int dd2 = 2 * l2 + 1, dd3 = 2 * l3 + 1;
    int i = flat / (dd2 * dd3), j = (flat / dd3) % dd2, k = flat % dd3;
    d_CG[idx] = realcg(l1, l2, l3, i, j, k);
}

// ---------------- weight interleave transpose ----------------
__global__ void transpose_kernel(const float* __restrict__ Wm3,
                                 const float* __restrict__ Wd0,
                                 const float* __restrict__ Wd1,
                                 const float* __restrict__ Wd2) {
    int idx = blockIdx.x * blockDim.x + threadIdx.x;
    if (idx < 53248) {
        int fi = idx & 3, ft = (idx >> 2) & 63, fo = (idx >> 8) & 15, m = idx >> 12;
        wm3t[idx] = Wm3[(4 * fo + fi) * 832 + m * 64 + ft];
    }
    if (idx < 36864) {
        int fi = idx & 3, t = (idx >> 2) % 192, mo = (idx >> 2) / 192;
        wd0t[idx] = Wd0[(4 * mo + fi) * 192 + t];
    }
    if (idx < 20480) {
        int fi = idx & 3, f = (idx >> 2) & 63, mo = idx >> 8;
        wd1t[idx] = Wd1[(4 * mo + fi) * 64 + f];
        wd2t[idx] = Wd2[(4 * mo + fi) * 64 + f];
    }
}

// ---------------- zero accumulators (vectorized) ----------------
__global__ void zero_acc_kernel() {
    float4* p = reinterpret_cast<float4*>(abuf);
    int n4 = NNODE * 2752 / 4;
    int i = blockIdx.x * blockDim.x + threadIdx.x;
    int stride = gridDim.x * blockDim.x;
    float4 z = make_float4(0.f, 0.f, 0.f, 0.f);
    for (int k = i; k < n4; k += stride) p[k] = z;
}

// ---------------- node prep: sc (-> out) and g projections ----------------
__global__ void node_prep_kernel(const float* __restrict__ nf,
                                 const int* __restrict__ specie,
                                 const float* __restrict__ Wsc0, const float* __restrict__ Wsc1,
                                 const float* __restrict__ Wsc2, const float* __restrict__ Wu0,
                                 const float* __restrict__ Wu1, const float* __restrict__ Wu2,
                                 float* __restrict__ out) {
    int n = blockIdx.x;
    int g = threadIdx.x;  // 64 threads
    __shared__ float sf[576];
    for (int i = g; i < 576; i += 64) sf[i] = nf[n * 576 + i];
    __syncthreads();
    int sp = specie[n];
    const float* w0p = Wsc0 + sp * 4096;
    const float* w1p = Wsc1 + sp * 4096;
    const float* w2p = Wsc2 + sp * 4096;

    float sc0 = 0.f, g0 = 0.f;
    float sc1[3] = {0.f, 0.f, 0.f}, g1[3] = {0.f, 0.f, 0.f};
    float sc2[5] = {0.f, 0.f, 0.f, 0.f, 0.f}, g2[5] = {0.f, 0.f, 0.f, 0.f, 0.f};
#pragma unroll 4
    for (int f = 0; f < 64; f++) {
        float w0 = w0p[f * 64 + g], u0 = Wu0[f * 64 + g];
        float w1 = w1p[f * 64 + g], u1 = Wu1[f * 64 + g];
        float w2 = w2p[f * 64 + g], u2 = Wu2[f * 64 + g];
        float v0 = sf[f];
        sc0 = fmaf(v0, w0, sc0);
        g0  = fmaf(v0, u0, g0);
#pragma unroll
        for (int c = 0; c < 3; c++) {
            float v = sf[64 + f * 3 + c];
            sc1[c] = fmaf(v, w1, sc1[c]);
            g1[c]  = fmaf(v, u1, g1[c]);
        }
#pragma unroll
        for (int c = 0; c < 5; c++) {
            float v = sf[256 + f * 5 + c];
            sc2[c] = fmaf(v, w2, sc2[c]);
            g2[c]  = fmaf(v, u2, g2[c]);
        }
    }
    const float invF = 0.125f;
    float* orow = out + (size_t)n * 576;
    orow[g] = sc0 * invF;
#pragma unroll
    for (int c = 0; c < 3; c++) orow[64 + g * 3 + c] = sc1[c] * invF;
#pragma unroll
    for (int c = 0; c < 5; c++) orow[256 + g * 5 + c] = sc2[c] * invF;
    g0buf[n * 64 + g] = g0 * invF;
#pragma unroll
    for (int c = 0; c < 3; c++) g1buf[n * 192 + c * 64 + g] = g1[c] * invF;
#pragma unroll
    for (int c = 0; c < 5; c++) g2buf[n * 320 + c * 64 + g] = g2[c] * invF;
}

__device__ __forceinline__ float swishf(float x) {
    return x / (1.0f + __expf(-x));
}

// ---------------- edge kernel: 16 edges / block, 256 threads (4 groups x 4 edges) ----
__global__ void __launch_bounds__(256, 4) edge_kernel(const float* __restrict__ vectors,
                            const int* __restrict__ senders,
                            const int* __restrict__ receivers,
                            const float* __restrict__ Wm1,
                            const float* __restrict__ Wm2) {
    __shared__ float h1[64 * 20];
    __shared__ float h2[64 * 20];
    __shared__ float sT[16 * 104];
    __shared__ float ssh[16 * 16];
    __shared__ float sradT[8 * 16];
    __shared__ float sx[16], sinvx[16];
    __shared__ int ssend[16], srecv[16], sact[16];

    int t = threadIdx.x;
    int ft = t & 63;
    int g = t >> 6;       // group g handles edges 4g..4g+3
    int e0 = blockIdx.x * 16;

    // ---- geometry ----
    if (t < 16) {
        int e = e0 + t;
        float vx = vectors[e * 3 + 0], vy = vectors[e * 3 + 1], vz = vectors[e * 3 + 2];
        float x = sqrtf(fmaxf(vx * vx + vy * vy + vz * vz, 1e-12f));
        float invx = 1.0f / x;
        float ux = vx * invx, uy = vy * invx, uz = vz * invx;
        sx[t] = x; sinvx[t] = invx;
        sact[t] = (x < 1.0f) ? 1 : 0;
        ssend[t] = senders[e];
        srecv[t] = receivers[e];
        float* sh = ssh + t * 16;
        const float s3 = 1.7320508075688772f;
        const float s15 = 3.872983346207417f;
        const float s5 = 2.23606797749979f;
        const float c35 = 2.091650066335189f;
        const float c105 = 10.246950765959598f;
        const float c21 = 1.6201851746019651f;
        const float c7 = 1.3228756555322954f;
        sh[0] = s3 * uy; sh[1] = s3 * uz; sh[2] = s3 * ux;
        sh[3] = s15 * ux * uy;
        sh[4] = s15 * uy * uz;
        sh[5] = 0.5f * s5 * (3.0f * uz * uz - 1.0f);
        sh[6] = s15 * ux * uz;
        sh[7] = 0.5f * s15 * (ux * ux - uy * uy);
        sh[8]  = c35 * uy * (3.0f * ux * ux - uy * uy);
        sh[9]  = c105 * ux * uy * uz;
        sh[10] = c21 * uy * (5.0f * uz * uz - 1.0f);
        sh[11] = c7 * uz * (5.0f * uz * uz - 3.0f);
        sh[12] = c21 * ux * (5.0f * uz * uz - 1.0f);
        sh[13] = 0.5f * c105 * uz * (ux * ux - uy * uy);
        sh[14] = c35 * ux * (ux * ux - 3.0f * uy * uy);
        sh[15] = 0.f;
    }
    __syncthreads();

    // ---- radial basis ----
    if (t < 128) {
        int e = t & 15, n = t >> 4;
        float x = sx[e];
        float env = 0.f;
        if (x < 1.0f) {
            float x2 = x * x, x4 = x2 * x2, x6 = x4 * x2, x7 = x6 * x, x8 = x7 * x;
            env = 1.0f - 28.0f * x6 + 48.0f * x7 - 21.0f * x8;
        }
        float nn = (float)(n + 1);
        sradT[n * 16 + e] = 1.41421356237f * sinf(3.14159265358979f * nn * x) * sinvx[e] * env;
    }
    __syncthreads();

    // ---- contracted CG tensors: sT[e][j] = sum_j' sh[e][j'] * C[i,j',k] ----
    for (int idx = t; idx < 16 * 102; idx += 256) {
        int e = idx / 102, j = idx % 102;
        const float* sh = ssh + e * 16;
        float v = 0.f;
        if (j < 3) {
            int i = j;
            for (int q = 0; q < 3; q++) v = fmaf(sh[q], d_CG[OFF110 + i * 3 + q], v);
        } else if (j < 8) {
            int i = j - 3;
            for (int q = 0; q < 5; q++) v = fmaf(sh[3 + q], d_CG[OFF220 + i * 5 + q], v);
        } else if (j < 17) {
            int ee = j - 8; int i = ee / 3, k = ee % 3;
            for (int q = 0; q < 5; q++) v = fmaf(sh[3 + q], d_CG[OFF121 + (i * 5 + q) * 3 + k], v);
        } else if (j < 32) {
            int ee = j - 17; int i = ee / 3, k = ee % 3;
            for (int q = 0; q < 3; q++) v = fmaf(sh[q], d_CG[OFF211 + (i * 3 + q) * 3 + k], v);
        } else if (j < 47) {
            int ee = j - 32; int i = ee / 3, k = ee % 3;
            for (int q = 0; q < 7; q++) v = fmaf(sh[8 + q], d_CG[OFF231 + (i * 7 + q) * 3 + k], v);
        } else if (j < 62) {
            int ee = j - 47; int i = ee / 5, k = ee % 5;
            for (int q = 0; q < 3; q++) v = fmaf(sh[q], d_CG[OFF112 + (i * 3 + q) * 5 + k], v);
        } else if (j < 77) {
            int ee = j - 62; int i = ee / 5, k = ee % 5;
            for (int q = 0; q < 7; q++) v = fmaf(sh[8 + q], d_CG[OFF132 + (i * 7 + q) * 5 + k], v);
        } else {
            int ee = j - 77; int i = ee / 5, k = ee % 5;
            for (int q = 0; q < 5; q++) v = fmaf(sh[3 + q], d_CG[OFF222 + (i * 5 + q) * 5 + k], v);
        }
        sT[e * 104 + j] = v;
    }
    __syncthreads();

    // ---- MLP layer 1: 8 -> 64 ----
    {
        float a0 = 0.f, a1 = 0.f, a2 = 0.f, a3 = 0.f;
#pragma unroll
        for (int i = 0; i < 8; i++) {
            float w = Wm1[i * 64 + ft];
            float4 r = *(const float4*)(sradT + i * 16 + 4 * g);
            a0 = fmaf(r.x, w, a0); a1 = fmaf(r.y, w, a1);
            a2 = fmaf(r.z, w, a2); a3 = fmaf(r.w, w, a3);
        }
        const float s8 = 0.35355339059327f;
        h1[ft * 20 + 4 * g + 0] = swishf(a0 * s8);
        h1[ft * 20 + 4 * g + 1] = swishf(a1 * s8);
        h1[ft * 20 + 4 * g + 2] = swishf(a2 * s8);
        h1[ft * 20 + 4 * g + 3] = swishf(a3 * s8);
    }
    __syncthreads();

    // ---- MLP layer 2: 64 -> 64 ----
    {
        float a0 = 0.f, a1 = 0.f, a2 = 0.f, a3 = 0.f;
#pragma unroll 8
        for (int f = 0; f < 64; f++) {
            float w = Wm2[f * 64 + ft];
            float4 hv = *(const float4*)(h1 + f * 20 + 4 * g);
            a0 = fmaf(hv.x, w, a0); a1 = fmaf(hv.y, w, a1);
            a2 = fmaf(hv.z, w, a2); a3 = fmaf(hv.w, w, a3);
        }
        const float s64 = 0.125f;
        h2[ft * 20 + 4 * g + 0] = swishf(a0 * s64);
        h2[ft * 20 + 4 * g + 1] = swishf(a1 * s64);
        h2[ft * 20 + 4 * g + 2] = swishf(a2 * s64);
        h2[ft * 20 + 4 * g + 3] = swishf(a3 * s64);
    }
    __syncthreads();

    const float msc = 0.125f * 0.316227766016838f;  // /sqrt(64) * 1/sqrt(AVG)
    const float4* wtv = (const float4*)wm3t;        // [(ch*16+fo)*64+ft]

    // ================= PASS A: channels {0,1,3,4,5,9,10,11} (s0/s1) =================
    {
        unsigned long long acc01[8], acc23[8];
#pragma unroll
        for (int q = 0; q < 8; q++) { acc01[q] = 0ull; acc23[q] = 0ull; }
#pragma unroll 2
        for (int fo = 0; fo < 16; fo++) {
            ulonglong2 hv0 = *(const ulonglong2*)(h2 + (4 * fo + 0) * 20 + 4 * g);
            ulonglong2 hv1 = *(const ulonglong2*)(h2 + (4 * fo + 1) * 20 + 4 * g);
            ulonglong2 hv2 = *(const ulonglong2*)(h2 + (4 * fo + 2) * 20 + 4 * g);
            ulonglong2 hv3 = *(const ulonglong2*)(h2 + (4 * fo + 3) * 20 + 4 * g);
            const float4* wb = wtv + fo * 64 + ft;
            float4 w4; unsigned long long wp;
#define GEMM4(Q, CH)                                                          \
            w4 = wb[(CH) * 1024];                                             \
            wp = pack2(w4.x);                                                 \
            acc01[Q] = fma2(hv0.x, wp, acc01[Q]);                             \
            acc23[Q] = fma2(hv0.y, wp, acc23[Q]);                             \
            wp = pack2(w4.y);                                                 \
            acc01[Q] = fma2(hv1.x, wp, acc01[Q]);                             \
            acc23[Q] = fma2(hv1.y, wp, acc23[Q]);                             \
            wp = pack2(w4.z);                                                 \
            acc01[Q] = fma2(hv2.x, wp, acc01[Q]);                             \
            acc23[Q] = fma2(hv2.y, wp, acc23[Q]);                             \
            wp = pack2(w4.w);                                                 \
            acc01[Q] = fma2(hv3.x, wp, acc01[Q]);                             \
            acc23[Q] = fma2(hv3.y, wp, acc23[Q]);
            GEMM4(0, 0) GEMM4(1, 1) GEMM4(2, 3) GEMM4(3, 4)
            GEMM4(4, 5) GEMM4(5, 9) GEMM4(6, 10) GEMM4(7, 11)
#undef GEMM4
        }
        float acc[8][4];
#pragma unroll
        for (int q = 0; q < 8; q++) {
            unpack2(acc01[q], acc[q][0], acc[q][1]);
            unpack2(acc23[q], acc[q][2], acc[q][3]);
#pragma unroll
            for (int el = 0; el < 4; el++) acc[q][el] *= msc;
        }

        // gather s0, s1 and scatter pass-A channels
#pragma unroll
        for (int el = 0; el < 4; el++) {
            int e = 4 * g + el;
            if (!sact[e]) continue;
            int sn = ssend[e];
            float* ap = abuf + (size_t)srecv[e] * 2752;
            const float* T = sT + e * 104;
            const float* sh = ssh + e * 16;
            float s0v = g0buf[sn * 64 + ft];
            float s1a = g1buf[sn * 192 + 0 * 64 + ft];
            float s1b = g1buf[sn * 192 + 1 * 64 + ft];
            float s1c = g1buf[sn * 192 + 2 * 64 + ft];

            atomicAdd(ap + ft, s0v * acc[0][el]);
            float tp110 = s1a * T[0] + s1b * T[1] + s1c * T[2];
            atomicAdd(ap + 64 + ft, tp110 * acc[1][el]);
#pragma unroll
            for (int c = 0; c < 3; c++) {
                float* p = ap + 192 + c * 320;
                float s1cc = (c == 0) ? s1a : ((c == 1) ? s1b : s1c);
                atomicAdd(p + ft, s1cc * acc[2][el]);
                atomicAdd(p + 64 + ft, s0v * sh[c] * acc[3][el]);
                float t121 = s1a * T[8 + c] + s1b * T[11 + c] + s1c * T[14 + c];
                atomicAdd(p + 128 + ft, t121 * acc[4][el]);
            }
#pragma unroll
            for (int c = 0; c < 5; c++) {
                float* p = ap + 1152 + c * 320;
                atomicAdd(p + 64 + ft, s0v * sh[3 + c] * acc[5][el]);
                float t112 = s1a * T[47 + c] + s1b * T[52 + c] + s1c * T[57 + c];
                atomicAdd(p + 128 + ft, t112 * acc[6][el]);
                float t132 = s1a * T[62 + c] + s1b * T[67 + c] + s1c * T[72 + c];
                atomicAdd(p + 192 + ft, t132 * acc[7][el]);
            }
        }
    }

    // ================= PASS B: channels {2,6,7,8,12} (s2) =================
    {
        unsigned long long acc01[5], acc23[5];
#pragma unroll
        for (int q = 0; q < 5; q++) { acc01[q] = 0ull; acc23[q] = 0ull; }
#pragma unroll 2
        for (int fo = 0; fo < 16; fo++) {
            ulonglong2 hv0 = *(const ulonglong2*)(h2 + (4 * fo + 0) * 20 + 4 * g);
            ulonglong2 hv1 = *(const ulonglong2*)(h2 + (4 * fo + 1) * 20 + 4 * g);
            ulonglong2 hv2 = *(const ulonglong2*)(h2 + (4 * fo + 2) * 20 + 4 * g);
            ulonglong2 hv3 = *(const ulonglong2*)(h2 + (4 * fo + 3) * 20 + 4 * g);
            const float4* wb = wtv + fo * 64 + ft;
            float4 w4; unsigned long long wp;
#define GEMM4(Q, CH)                                                          \
            w4 = wb[(CH) * 1024];                                             \
            wp = pack2(w4.x);                                                 \
            acc01[Q] = fma2(hv0.x, wp, acc01[Q]);                             \
            acc23[Q] = fma2(hv0.y, wp, acc23[Q]);                             \
            wp = pack2(w4.y);                                                 \
            acc01[Q] = fma2(hv1.x, wp, acc01[Q]);                             \
            acc23[Q] = fma2(hv1.y, wp, acc23[Q]);                             \
            wp = pack2(w4.z);                                                 \
            acc01[Q] = fma2(hv2.x, wp, acc01[Q]);                             \
            acc23[Q] = fma2(hv2.y, wp, acc23[Q]);                             \
            wp = pack2(w4.w);                                                 \
            acc01[Q] = fma2(hv3.x, wp, acc01[Q]);                             \
            acc23[Q] = fma2(hv3.y, wp, acc23[Q]);
            GEMM4(0, 2) GEMM4(1, 6) GEMM4(2, 7) GEMM4(3, 8) GEMM4(4, 12)
#undef GEMM4
        }
        float acc[5][4];
#pragma unroll
        for (int q = 0; q < 5; q++) {
            unpack2(acc01[q], acc[q][0], acc[q][1]);
            unpack2(acc23[q], acc[q][2], acc[q][3]);
#pragma unroll
            for (int el = 0; el < 4; el++) acc[q][el] *= msc;
        }

#pragma unroll
        for (int el = 0; el < 4; el++) {
            int e = 4 * g + el;
            if (!sact[e]) continue;
            int sn = ssend[e];
            float* ap = abuf + (size_t)srecv[e] * 2752;
            const float* T = sT + e * 104;
            float s2v[5];
#pragma unroll
            for (int c = 0; c < 5; c++) s2v[c] = g2buf[sn * 320 + c * 64 + ft];

            float tp220 = 0.f;
#pragma unroll
            for (int i = 0; i < 5; i++) tp220 = fmaf(s2v[i], T[3 + i], tp220);
            atomicAdd(ap + 128 + ft, tp220 * acc[0][el]);

#pragma unroll
            for (int c = 0; c < 3; c++) {
                float* p = ap + 192 + c * 320;
                float t211 = 0.f, t231 = 0.f;
#pragma unroll
                for (int i = 0; i < 5; i++) {
                    t211 = fmaf(s2v[i], T[17 + i * 3 + c], t211);
                    t231 = fmaf(s2v[i], T[32 + i * 3 + c], t231);
                }
                atomicAdd(p + 192 + ft, t211 * acc[1][el]);
                atomicAdd(p + 256 + ft, t231 * acc[2][el]);
            }
#pragma unroll
            for (int c = 0; c < 5; c++) {
                float* p = ap + 1152 + c * 320;
                atomicAdd(p + ft, s2v[c] * acc[3][el]);
                float t222 = 0.f;
#pragma unroll
                for (int i = 0; i < 5; i++) t222 = fmaf(s2v[i], T[77 + i * 5 + c], t222);
                atomicAdd(p + 256 + ft, t222 * acc[4][el]);
            }
        }
    }
}

// ---------------- node output: 4 nodes / block, 320 threads ----------------
__global__ void __launch_bounds__(320) node_out_kernel(float* __restrict__ out) {
    int n0 = blockIdx.x * 4;
    int t = threadIdx.x;
    __shared__ float saT[2752 * 4];
    __shared__ float sd0[4 * 192];

    for (int j = t; j < 2752; j += 320) {
#pragma unroll
        for (int nn = 0; nn < 4; nn++)
            saT[j * 4 + nn] = abuf[(size_t)(n0 + nn) * 2752 + j];
    }
    __syncthreads();

    // d0: 192 -> 192 (48 chunks of 4 m)
    if (t < 192) {
        unsigned long long a01 = 0ull, a23 = 0ull;
        const float4* wb = ((const float4*)wd0t) + t;
#pragma unroll 4
        for (int mo = 0; mo < 48; mo++) {
            float4 w4 = wb[mo * 192];
            ulonglong2 av0 = *(const ulonglong2*)(saT + (4 * mo + 0) * 4);
            ulonglong2 av1 = *(const ulonglong2*)(saT + (4 * mo + 1) * 4);
            ulonglong2 av2 = *(const ulonglong2*)(saT + (4 * mo + 2) * 4);
            ulonglong2 av3 = *(const ulonglong2*)(saT + (4 * mo + 3) * 4);
            unsigned long long wp;
            wp = pack2(w4.x); a01 = fma2(av0.x, wp, a01); a23 = fma2(av0.y, wp, a23);
            wp = pack2(w4.y); a01 = fma2(av1.x, wp, a01); a23 = fma2(av1.y, wp, a23);
            wp = pack2(w4.z); a01 = fma2(av2.x, wp, a01); a23 = fma2(av2.y, wp, a23);
            wp = pack2(w4.w); a01 = fma2(av3.x, wp, a01); a23 = fma2(av3.y, wp, a23);
        }
        float r0, r1, r2, r3;
        unpack2(a01, r0, r1); unpack2(a23, r2, r3);
        const float s = 0.0721687836487032f;  // 1/sqrt(192)
        sd0[0 * 192 + t] = swishf(r0 * s);
        sd0[1 * 192 + t] = swishf(r1 * s);
        sd0[2 * 192 + t] = swishf(r2 * s);
        sd0[3 * 192 + t] = swishf(r3 * s);
    }
    __syncthreads();

    if (t < 64) {
#pragma unroll
        for (int nn = 0; nn < 4; nn++)
            out[(size_t)(n0 + nn) * 576 + t] += sd0[nn * 192 + t];
    }

    const float s320 = 0.0559016994374947f;  // 1/sqrt(320)

    // d1: a1[c][320] @ Wd1[320][64], gated (80 chunks of 4 m)
    if (t < 192) {
        int c = t / 64, f = t % 64;
        unsigned long long a01 = 0ull, a23 = 0ull;
        const float4* wb = ((const float4*)wd1t) + f;
        const float* base = saT + (192 + c * 320) * 4;
#pragma unroll 4
        for (int mo = 0; mo < 80; mo++) {
            float4 w4 = wb[mo * 64];
            ulonglong2 av0 = *(const ulonglong2*)(base + (4 * mo + 0) * 4);
            ulonglong2 av1 = *(const ulonglong2*)(base + (4 * mo + 1) * 4);
            ulonglong2 av2 = *(const ulonglong2*)(base + (4 * mo + 2) * 4);
            ulonglong2 av3 = *(const ulonglong2*)(base + (4 * mo + 3) * 4);
            unsigned long long wp;
            wp = pack2(w4.x); a01 = fma2(av0.x, wp, a01); a23 = fma2(av0.y, wp, a23);
            wp = pack2(w4.y); a01 = fma2(av1.x, wp, a01); a23 = fma2(av1.y, wp, a23);
            wp = pack2(w4.z); a01 = fma2(av2.x, wp, a01); a23 = fma2(av2.y, wp, a23);
            wp = pack2(w4.w); a01 = fma2(av3.x, wp, a01); a23 = fma2(av3.y, wp, a23);
        }
        float r[4];
        unpack2(a01, r[0], r[1]); unpack2(a23, r[2], r[3]);
#pragma unroll
        for (int nn = 0; nn < 4; nn++)
            out[(size_t)(n0 + nn) * 576 + 64 + f * 3 + c] += r[nn] * s320 * sd0[nn * 192 + 64 + f];
    }

    // d2: a2[c][320] @ Wd2[320][64], gated
    {
        int c = t / 64, f = t % 64;
        unsigned long long a01 = 0ull, a23 = 0ull;
        const float4* wb = ((const float4*)wd2t) + f;
        const float* base = saT + (1152 + c * 320) * 4;
#pragma unroll 4
        for (int mo = 0; mo < 80; mo++) {
            float4 w4 = wb[mo * 64];
            ulonglong2 av0 = *(const ulonglong2*)(base + (4 * mo + 0) * 4);
            ulonglong2 av1 = *(const ulonglong2*)(base + (4 * mo + 1) * 4);
            ulonglong2 av2 = *(const ulonglong2*)(base + (4 * mo + 2) * 4);
            ulonglong2 av3 = *(const ulonglong2*)(base + (4 * mo + 3) * 4);
            unsigned long long wp;
            wp = pack2(w4.x); a01 = fma2(av0.x, wp, a01); a23 = fma2(av0.y, wp, a23);
            wp = pack2(w4.y); a01 = fma2(av1.x, wp, a01); a23 = fma2(av1.y, wp, a23);
            wp = pack2(w4.z); a01 = fma2(av2.x, wp, a01); a23 = fma2(av2.y, wp, a23);
            wp = pack2(w4.w); a01 = fma2(av3.x, wp, a01); a23 = fma2(av3.y, wp, a23);
        }
        float r[4];
        unpack2(a01, r[0], r[1]); unpack2(a23, r[2], r[3]);
#pragma unroll
        for (int nn = 0; nn < 4; nn++)
            out[(size_t)(n0 + nn) * 576 + 256 + f * 5 + c] += r[nn] * s320 * sd0[nn * 192 + 128 + f];
    }
}

// ---------------- launcher ----------------
extern "C" void kernel_launch(void* const* d_in, const int* in_sizes, int n_in,
                              void* d_out, int out_size) {
    const float* vectors    = (const float*)d_in[0];
    const float* node_feats = (const float*)d_in[1];
    const int*   node_specie= (const int*)d_in[2];
    const int*   senders    = (const int*)d_in[3];
    const int*   receivers  = (const int*)d_in[4];
    const float* Wsc0 = (const float*)d_in[5];
    const float* Wsc1 = (const float*)d_in[6];
    const float* Wsc2 = (const float*)d_in[7];
    const float* Wu0  = (const float*)d_in[8];
    const float* Wu1  = (const float*)d_in[9];
    const float* Wu2  = (const float*)d_in[10];
    const float* Wm1  = (const float*)d_in[11];
    const float* Wm2  = (const float*)d_in[12];
    const float* Wm3  = (const float*)d_in[13];
    const float* Wd0  = (const float*)d_in[14];
    const float* Wd1  = (const float*)d_in[15];
    const float* Wd2  = (const float*)d_in[16];
    float* out = (float*)d_out;

    cg_init_kernel<<<16, 32>>>();
    transpose_kernel<<<208, 256>>>(Wm3, Wd0, Wd1, Wd2);
    zero_acc_kernel<<<2048, 256>>>();
    node_prep_kernel<<<NNODE, 64>>>(node_feats, node_specie, Wsc0, Wsc1, Wsc2,
                                    Wu0, Wu1, Wu2, out);
    edge_kernel<<<NEDGE / 16, 256>>>(vectors, senders, receivers, Wm1, Wm2);
    node_out_kernel<<<NNODE / 4, 320>>>(out);
}